// round 7
// baseline (speedup 1.0000x reference)
#include <cuda_runtime.h>
#include <cstdint>
#include <cstddef>

#define TSTEPS 1024
#define BATCH  128
#define DIN    64
#define HH     512
#define NG     16         // row groups (8 rows each)
#define NC     8          // CTAs per cluster (64-col slices)
#define RG     8          // rows per group
#define CW     64         // cols per CTA
#define NTHR   512
#define HP     12         // float pitch per k-row (8 rows + 4 pad)
#define EPSF   1e-5f

#define CHK_K      64                 // k-rows per weight chunk
#define CHK_FL     (CHK_K * CW)       // 4096 floats = 16KB
#define NBUF       3
#define CH_S0      9                  // stage0 chunks (Wi0:1 + Wh0:8)
#define CH_STEP    25                 // chunks per step (9 + 16)
#define TOT_CHK    (CH_STEP * TSTEPS)

// ---- shared memory layout (float offsets) ----
#define OF_RING   0
#define OF_H0X    (OF_RING + NBUF * CHK_FL)       // 12288
#define OF_H1X    (OF_H0X + 576 * HP)             // +6912
#define OF_RED    (OF_H1X + 512 * HP)             // +6144
#define OF_INBOX  (OF_RED + 16 * 32 * 18)         // +9216
#define OF_PART   (OF_INBOX + 2 * RG * HH)        // +8192 ; part[st][rank][row] float2
#define OF_SG0    (OF_PART + 2 * NC * RG * 2)     // +256
#define OF_SB0    (OF_SG0 + HH)
#define OF_SG1    (OF_SB0 + HH)
#define OF_SB1    (OF_SG1 + HH)
#define OF_CB0    (OF_SB1 + HH)
#define OF_CB1    (OF_CB0 + CW)
#define OF_SP     (OF_CB1 + CW)                   // sp[row][half] float2 -> 32 floats
#define OF_SMU    (OF_SP + 32)
#define OF_SRS    (OF_SMU + RG)
#define SMEM_FL   (OF_SRS + RG)
#define SMEM_BYTES (SMEM_FL * 4)

typedef unsigned long long ull;

__device__ __forceinline__ ull ffma2(ull a, ull b, ull c) {
    ull d;
    asm("fma.rn.f32x2 %0, %1, %2, %3;" : "=l"(d) : "l"(a), "l"(b), "l"(c));
    return d;
}
__device__ __forceinline__ ull dup2(float f) {
    ull d;
    asm("mov.b64 %0, {%1, %1};" : "=l"(d) : "f"(f));
    return d;
}
__device__ __forceinline__ uint32_t smem_u32(const void* p) {
    uint32_t a;
    asm("{ .reg .u64 t; cvta.to.shared.u64 t, %1; cvt.u32.u64 %0, t; }" : "=r"(a) : "l"(p));
    return a;
}
__device__ __forceinline__ void cp_async16(uint32_t dst, const float* src) {
    asm volatile("cp.async.cg.shared.global [%0], [%1], 16;" :: "r"(dst), "l"(src) : "memory");
}
__device__ __forceinline__ void cp_commit() {
    asm volatile("cp.async.commit_group;" ::: "memory");
}
__device__ __forceinline__ void cp_wait2() {
    asm volatile("cp.async.wait_group 2;" ::: "memory");
}
__device__ __forceinline__ void st_cluster_v4(uint32_t laddr, int rank, float4 v) {
    uint32_t ra;
    asm volatile("mapa.shared::cluster.u32 %0, %1, %2;" : "=r"(ra) : "r"(laddr), "r"(rank));
    asm volatile("st.shared::cluster.v4.b32 [%0], {%1,%2,%3,%4};"
                 :: "r"(ra), "r"(__float_as_uint(v.x)), "r"(__float_as_uint(v.y)),
                    "r"(__float_as_uint(v.z)), "r"(__float_as_uint(v.w)) : "memory");
}
__device__ __forceinline__ void st_cluster_b64(uint32_t laddr, int rank, ull v) {
    uint32_t ra;
    asm volatile("mapa.shared::cluster.u32 %0, %1, %2;" : "=r"(ra) : "r"(laddr), "r"(rank));
    asm volatile("st.shared::cluster.b64 [%0], %1;" :: "r"(ra), "l"(v) : "memory");
}
__device__ __forceinline__ uint32_t ctarank() {
    uint32_t r;
    asm("mov.u32 %0, %%cluster_ctarank;" : "=r"(r));
    return r;
}
#define CLUSTER_SYNC() do { \
    asm volatile("barrier.cluster.arrive.aligned;" ::: "memory"); \
    asm volatile("barrier.cluster.wait.aligned;" ::: "memory"); } while (0)

__global__ void __launch_bounds__(NTHR, 1) __cluster_dims__(NC, 1, 1)
rnn_cluster_kernel(
    const float* __restrict__ x,
    const float* __restrict__ Wi0, const float* __restrict__ bi0,
    const float* __restrict__ Wh0, const float* __restrict__ bh0,
    const float* __restrict__ g0,  const float* __restrict__ be0,
    const float* __restrict__ Wi1, const float* __restrict__ bi1,
    const float* __restrict__ Wh1, const float* __restrict__ bh1,
    const float* __restrict__ g1,  const float* __restrict__ be1,
    const float* __restrict__ Wfc, const float* __restrict__ bfc,
    float* __restrict__ out)
{
    extern __shared__ float sm[];
    float* ring  = sm + OF_RING;
    float* h0x   = sm + OF_H0X;     // [576][HP]: rows 0..63 = x_t, 64..575 = h0n
    float* h1x   = sm + OF_H1X;     // [512][HP]
    float* red   = sm + OF_RED;     // [16 phases][32 lanes][18]
    float* inbox = sm + OF_INBOX;   // [2][8 rows][512 cols]
    float2* part = (float2*)(sm + OF_PART);  // [2][NC][RG]
    float* sg0   = sm + OF_SG0;  float* sb0 = sm + OF_SB0;
    float* sg1   = sm + OF_SG1;  float* sb1 = sm + OF_SB1;
    float* cb0   = sm + OF_CB0;  float* cb1 = sm + OF_CB1;
    float2* sp   = (float2*)(sm + OF_SP);    // [RG][2]
    float* smu   = sm + OF_SMU;  float* srs = sm + OF_SRS;

    const int tid  = threadIdx.x;
    const int lane = tid & 31;
    const int p    = tid >> 5;          // k-phase warp 0..15
    const int cg   = lane & 15;         // col group (4 cols)
    const int rq   = lane >> 4;         // row quad 0..1 (rows 4rq..4rq+3)
    const int rank = (int)ctarank();
    const int g    = blockIdx.x >> 3;   // row group
    const int c0   = rank * CW;
    const int row0 = g * RG;

    const uint32_t ring_b = smem_u32(ring);
    const uint32_t inbox_b = smem_u32(inbox);
    const uint32_t part_b = smem_u32(part);

    // ---- init ----
    sg0[tid] = g0[tid];  sb0[tid] = be0[tid];
    sg1[tid] = g1[tid];  sb1[tid] = be1[tid];
    if (tid < CW) {
        cb0[tid] = bi0[c0 + tid] + bh0[c0 + tid];
        cb1[tid] = bi1[c0 + tid] + bh1[c0 + tid];
    }
    for (int i = tid; i < 576 * HP; i += NTHR) h0x[i] = 0.f;
    for (int i = tid; i < 512 * HP; i += NTHR) h1x[i] = 0.f;
    __syncthreads();
    CLUSTER_SYNC();   // peers' smem ready before any DSMEM store

    // epilogue constants
    const int erow = tid >> 6;          // 0..7
    const int ecol = tid & 63;
    const int lane_src = ((erow >> 2) << 4) | (ecol >> 2);
    const float* rrd = red + lane_src * 18 + 4 * (erow & 3) + (ecol & 3);

    // ---- weight pipeline bootstrap: issue chunks 0,1 ----
    int bufc = 0;
    {
#pragma unroll
        for (int cc = 0; cc < 2; ++cc) {
            const float* src = (cc == 0) ? (Wi0 + c0) : (Wh0 + c0);  // chunk0=Wi0 rows0..63, chunk1=Wh0 rows0..63
#pragma unroll
            for (int u = 0; u < 2; ++u) {
                int o = tid + u * NTHR;
                int r = o >> 4, cw = o & 15;
                cp_async16(ring_b + (uint32_t)((cc * CHK_FL + r * CW + cw * 4) * 4),
                           src + (size_t)r * HH + cw * 4);
            }
            cp_commit();
        }
    }

    for (int t = 0; t < TSTEPS; ++t) {
        // ---- stage x_t into h0x rows 0..63 (plain) ----
        {
            int r = tid >> 6, k = tid & 63;
            h0x[k * HP + r] = x[((size_t)(row0 + r) * TSTEPS + t) * DIN + k];
        }

        ull acc[8];
#pragma unroll
        for (int q = 0; q < 8; ++q) acc[q] = 0ull;

        for (int c = 0; c < CH_STEP; ++c) {
            // ---------- pipelined chunk iteration ----------
            __syncthreads();                    // prior compute done before ring overwrite
            int gi = t * CH_STEP + c + 2;
            if (gi < TOT_CHK) {
                int s = (c + 2 < CH_STEP) ? (c + 2) : (c + 2 - CH_STEP);
                const float* src;
                if (s == 0)       src = Wi0 + c0;
                else if (s <= 8)  src = Wh0 + (size_t)((s - 1) * CHK_K) * HH + c0;
                else if (s <= 16) src = Wi1 + (size_t)((s - 9) * CHK_K) * HH + c0;
                else              src = Wh1 + (size_t)((s - 17) * CHK_K) * HH + c0;
                int bi = bufc + 2; if (bi >= NBUF) bi -= NBUF;
                uint32_t db = ring_b + (uint32_t)(bi * CHK_FL * 4);
#pragma unroll
                for (int u = 0; u < 2; ++u) {
                    int o = tid + u * NTHR;
                    int r = o >> 4, cw = o & 15;
                    cp_async16(db + (uint32_t)((r * CW + cw * 4) * 4),
                               src + (size_t)r * HH + cw * 4);
                }
            }
            cp_commit();
            cp_wait2();
            __syncthreads();                    // chunk c visible to all

            // ---------- compute chunk c ----------
            const float* hb;
            if (c < CH_S0)      hb = h0x + c * CHK_K * HP;
            else if (c < 17)    hb = h0x + (64 + (c - CH_S0) * CHK_K) * HP;
            else                hb = h1x + (c - 17) * CHK_K * HP;
            const float* wb = ring + bufc * CHK_FL + 4 * cg;
#pragma unroll
            for (int i = 0; i < 4; ++i) {
                int kl = p + 16 * i;
                ulonglong2 w = *(const ulonglong2*)(wb + kl * CW);
                float4 hv = *(const float4*)(hb + kl * HP + 4 * rq);
                ull d0 = dup2(hv.x), d1 = dup2(hv.y), d2 = dup2(hv.z), d3 = dup2(hv.w);
                acc[0] = ffma2(d0, w.x, acc[0]); acc[1] = ffma2(d0, w.y, acc[1]);
                acc[2] = ffma2(d1, w.x, acc[2]); acc[3] = ffma2(d1, w.y, acc[3]);
                acc[4] = ffma2(d2, w.x, acc[4]); acc[5] = ffma2(d2, w.y, acc[5]);
                acc[6] = ffma2(d3, w.x, acc[6]); acc[7] = ffma2(d3, w.y, acc[7]);
            }
            bufc = (bufc + 1 < NBUF) ? bufc + 1 : 0;

            // ---------- stage boundary epilogues ----------
            if (c == CH_S0 - 1 || c == CH_STEP - 1) {
                const int st = (c == CH_S0 - 1) ? 0 : 1;
                // dump acc -> red
                {
                    float* rw = red + p * 576 + lane * 18;
#pragma unroll
                    for (int q = 0; q < 8; ++q) *(ull*)(rw + 2 * q) = acc[q];
                }
                __syncthreads();
                // epilogue: z -> tanh -> +residual -> inbox + partials
                {
                    float z = 0.f;
#pragma unroll
                    for (int p2 = 0; p2 < 16; ++p2) z += rrd[p2 * 576];
                    float hold;
                    if (st == 0) { z += cb0[ecol]; hold = h0x[(64 + c0 + ecol) * HP + erow]; }
                    else         { z += cb1[ecol]; hold = h1x[(c0 + ecol) * HP + erow]; }
                    float cv = tanhf(z) + hold;
                    inbox[st * RG * HH + erow * HH + c0 + ecol] = cv;
                    float s = cv, q = cv * cv;
#pragma unroll
                    for (int o = 16; o; o >>= 1) {
                        s += __shfl_xor_sync(0xffffffffu, s, o);
                        q += __shfl_xor_sync(0xffffffffu, q, o);
                    }
                    if (lane == 0) sp[(p >> 1) * 2 + (p & 1)] = make_float2(s, q);
                }
                __syncthreads();
                // broadcast own slice (float4) + partials to 7 peers
                if (tid < 128) {
                    int rr = tid >> 4, cgi = tid & 15;
                    uint32_t off = (uint32_t)((st * RG * HH + rr * HH + c0 + 4 * cgi) * 4);
                    float4 v = *(const float4*)(inbox + st * RG * HH + rr * HH + c0 + 4 * cgi);
#pragma unroll
                    for (int d = 1; d < NC; ++d)
                        st_cluster_v4(inbox_b + off, (rank + d) & (NC - 1), v);
                }
                if (tid < RG) {
                    float2 a = sp[tid * 2], b = sp[tid * 2 + 1];
                    float2 pv = make_float2(a.x + b.x, a.y + b.y);
                    part[(st * NC + rank) * RG + tid] = pv;
                    uint32_t off = (uint32_t)(((st * NC + rank) * RG + tid) * 8);
                    ull pb = *(ull*)&pv;
#pragma unroll
                    for (int d = 1; d < NC; ++d)
                        st_cluster_b64(part_b + off, (rank + d) & (NC - 1), pb);
                }
                CLUSTER_SYNC();
                // LN stats (redundant in every CTA)
                if (tid < 64) {
                    int w2 = tid >> 5, l = tid & 31;
                    int r = 4 * w2 + (l >> 3), s8 = l & 7;
                    float2 pv = part[(st * NC + s8) * RG + r];
#pragma unroll
                    for (int o = 4; o; o >>= 1) {
                        pv.x += __shfl_xor_sync(0xffffffffu, pv.x, o);
                        pv.y += __shfl_xor_sync(0xffffffffu, pv.y, o);
                    }
                    if (s8 == 0) {
                        float mu = pv.x * (1.f / HH);
                        float var = pv.y * (1.f / HH) - mu * mu;
                        smu[r] = mu; srs[r] = rsqrtf(var + EPSF);
                    }
                }
                __syncthreads();
                // rebuild full normalized h (plain) locally
                {
                    const float* gam = st ? sg1 : sg0;
                    const float* bet = st ? sb1 : sb0;
                    float* hdst = st ? (h1x + tid * HP) : (h0x + (64 + tid) * HP);
                    const float* ib = inbox + st * RG * HH + tid;
                    float gk = gam[tid], bk = bet[tid];
#pragma unroll
                    for (int r = 0; r < RG; ++r)
                        hdst[r] = (ib[r * HH] - smu[r]) * srs[r] * gk + bk;
                }
                __syncthreads();
#pragma unroll
                for (int q = 0; q < 8; ++q) acc[q] = 0ull;  // reset for next stage
            }
        }
    }

    // ======== output head (rank 0 CTA of each group) ========
    if (rank == 0 && p < RG) {
        float v = 0.f;
#pragma unroll
        for (int m = 0; m < 16; ++m) {
            int k = lane + 32 * m;
            v += h1x[k * HP + p] * Wfc[k];
        }
#pragma unroll
        for (int o = 16; o; o >>= 1) v += __shfl_xor_sync(0xffffffffu, v, o);
        if (lane == 0) out[row0 + p] = v + bfc[0];
    }
}

extern "C" void kernel_launch(void* const* d_in, const int* in_sizes, int n_in,
                              void* d_out, int out_size) {
    (void)in_sizes; (void)n_in; (void)out_size;
    const float* x   = (const float*)d_in[0];
    const float* Wi0 = (const float*)d_in[1];
    const float* bi0 = (const float*)d_in[2];
    const float* Wh0 = (const float*)d_in[3];
    const float* bh0 = (const float*)d_in[4];
    const float* g0  = (const float*)d_in[5];
    const float* be0 = (const float*)d_in[6];
    const float* Wi1 = (const float*)d_in[7];
    const float* bi1 = (const float*)d_in[8];
    const float* Wh1 = (const float*)d_in[9];
    const float* bh1 = (const float*)d_in[10];
    const float* g1  = (const float*)d_in[11];
    const float* be1 = (const float*)d_in[12];
    const float* Wfc = (const float*)d_in[13];
    const float* bfc = (const float*)d_in[14];

    static int inited = 0;
    if (!inited) {
        cudaFuncSetAttribute(rnn_cluster_kernel,
                             cudaFuncAttributeMaxDynamicSharedMemorySize, SMEM_BYTES);
        inited = 1;
    }
    rnn_cluster_kernel<<<NG * NC, NTHR, SMEM_BYTES>>>(
        x, Wi0, bi0, Wh0, bh0, g0, be0,
        Wi1, bi1, Wh1, bh1, g1, be1,
        Wfc, bfc, (float*)d_out);
}

// round 8
// speedup vs baseline: 1.7962x; 1.7962x over previous
#include <cuda_runtime.h>
#include <cstdint>
#include <cstddef>

#define TSTEPS 1024
#define BATCH  128
#define DIN    64
#define HH     512
#define NGRP   16        // row groups (8 rows each)
#define NC     8         // CTAs per cluster (64-col slices)
#define RG     8         // rows per group
#define CW     64        // cols per CTA slice
#define NTHR   512
#define HP     12        // float pitch per k-row (8 rows + 4 pad, keeps 16B align)
#define EPSF   1e-5f

// ---- shared memory layout (float offsets) ----
#define OF_H0X   0                         // [576][HP]: rows 0..63 = x_t, 64..575 = h0n
#define OF_H1X   (OF_H0X + 576 * HP)       // [512][HP]
#define OF_RED   (OF_H1X + 512 * HP)       // [16][32][18]
#define OF_INBOX (OF_RED + 16 * 32 * 18)   // [2][RG][HH]
#define OF_PART  (OF_INBOX + 2 * RG * HH)  // [2][NC][RG] float2
#define OF_SG0   (OF_PART + 2 * NC * RG * 2)
#define OF_SB0   (OF_SG0 + HH)
#define OF_SG1   (OF_SB0 + HH)
#define OF_SB1   (OF_SG1 + HH)
#define OF_CB0   (OF_SB1 + HH)
#define OF_CB1   (OF_CB0 + CW)
#define OF_SP    (OF_CB1 + CW)             // [16] float2
#define OF_SMU   (OF_SP + 32)
#define OF_SRS   (OF_SMU + RG)
#define SMEM_FL  (OF_SRS + RG)
#define SMEM_BYTES (SMEM_FL * 4)

typedef unsigned long long ull;

__device__ __forceinline__ ull ffma2(ull a, ull b, ull c) {
    ull d;
    asm("fma.rn.f32x2 %0, %1, %2, %3;" : "=l"(d) : "l"(a), "l"(b), "l"(c));
    return d;
}
__device__ __forceinline__ ull dup2(float f) {
    ull d;
    asm("mov.b64 %0, {%1, %1};" : "=l"(d) : "f"(f));
    return d;
}
__device__ __forceinline__ uint32_t smem_u32(const void* p) {
    uint32_t a;
    asm("{ .reg .u64 t; cvta.to.shared.u64 t, %1; cvt.u32.u64 %0, t; }" : "=r"(a) : "l"(p));
    return a;
}
__device__ __forceinline__ void st_cluster_v4(uint32_t laddr, int rank, float4 v) {
    uint32_t ra;
    asm volatile("mapa.shared::cluster.u32 %0, %1, %2;" : "=r"(ra) : "r"(laddr), "r"(rank));
    asm volatile("st.shared::cluster.v4.b32 [%0], {%1,%2,%3,%4};"
                 :: "r"(ra), "r"(__float_as_uint(v.x)), "r"(__float_as_uint(v.y)),
                    "r"(__float_as_uint(v.z)), "r"(__float_as_uint(v.w)) : "memory");
}
__device__ __forceinline__ void st_cluster_b64(uint32_t laddr, int rank, ull v) {
    uint32_t ra;
    asm volatile("mapa.shared::cluster.u32 %0, %1, %2;" : "=r"(ra) : "r"(laddr), "r"(rank));
    asm volatile("st.shared::cluster.b64 [%0], %1;" :: "r"(ra), "l"(v) : "memory");
}
__device__ __forceinline__ uint32_t ctarank() {
    uint32_t r;
    asm("mov.u32 %0, %%cluster_ctarank;" : "=r"(r));
    return r;
}
#define CL_ARRIVE() asm volatile("barrier.cluster.arrive.aligned;" ::: "memory")
#define CL_WAIT()   asm volatile("barrier.cluster.wait.aligned;" ::: "memory")

// GEMV slice: ITERS k-steps (k = p + 16*i), 4 cols x 4 rows per thread.
// W from global (L2), h plain floats from smem (dup2 to f32x2 pairs).
template<int ITERS>
__device__ __forceinline__ void gpart(const float* __restrict__ Wp,
                                      const float* __restrict__ hp, ull* acc) {
#pragma unroll 8
    for (int i = 0; i < ITERS; ++i) {
        ulonglong2 w = *(const ulonglong2*)(Wp + (size_t)i * 16 * HH);
        float4 hv = *(const float4*)(hp + i * 16 * HP);
        ull d0 = dup2(hv.x), d1 = dup2(hv.y), d2 = dup2(hv.z), d3 = dup2(hv.w);
        acc[0] = ffma2(d0, w.x, acc[0]); acc[1] = ffma2(d0, w.y, acc[1]);
        acc[2] = ffma2(d1, w.x, acc[2]); acc[3] = ffma2(d1, w.y, acc[3]);
        acc[4] = ffma2(d2, w.x, acc[4]); acc[5] = ffma2(d2, w.y, acc[5]);
        acc[6] = ffma2(d3, w.x, acc[6]); acc[7] = ffma2(d3, w.y, acc[7]);
    }
}

__global__ void __launch_bounds__(NTHR, 1) __cluster_dims__(NC, 1, 1)
rnn_overlap_kernel(
    const float* __restrict__ x,
    const float* __restrict__ Wi0, const float* __restrict__ bi0,
    const float* __restrict__ Wh0, const float* __restrict__ bh0,
    const float* __restrict__ g0,  const float* __restrict__ be0,
    const float* __restrict__ Wi1, const float* __restrict__ bi1,
    const float* __restrict__ Wh1, const float* __restrict__ bh1,
    const float* __restrict__ g1,  const float* __restrict__ be1,
    const float* __restrict__ Wfc, const float* __restrict__ bfc,
    float* __restrict__ out)
{
    extern __shared__ float sm[];
    float*  h0x   = sm + OF_H0X;
    float*  h1x   = sm + OF_H1X;
    float*  red   = sm + OF_RED;
    float*  inbox = sm + OF_INBOX;
    float2* part  = (float2*)(sm + OF_PART);
    float*  sg0   = sm + OF_SG0;  float* sb0 = sm + OF_SB0;
    float*  sg1   = sm + OF_SG1;  float* sb1 = sm + OF_SB1;
    float*  cb0   = sm + OF_CB0;  float* cb1 = sm + OF_CB1;
    float2* sp    = (float2*)(sm + OF_SP);
    float*  smu   = sm + OF_SMU;  float* srs = sm + OF_SRS;

    const int tid  = threadIdx.x;
    const int lane = tid & 31;
    const int p    = tid >> 5;          // warp = k-phase (16)
    const int cgo  = (lane & 15) * 4;   // col offset within slice (4-col group)
    const int rqo  = (lane >> 4) * 4;   // row offset (4-row quad)
    const int rank = (int)ctarank();
    const int g    = blockIdx.x >> 3;
    const int c0   = rank * CW;
    const int row0 = g * RG;

    const uint32_t inbox_b = smem_u32(inbox);
    const uint32_t part_b  = smem_u32(part);

    // epilogue constants
    const int erow = tid >> 6;          // 0..7
    const int ecol = tid & 63;          // 0..63
    const float* rrd = red + (((erow >> 2) << 4) | (ecol >> 2)) * 18
                           + 4 * (erow & 3) + (ecol & 3);

    // per-thread GEMV base pointers
    const float* wp_i0 = Wi0 + c0 + (size_t)p * HH + cgo;
    const float* wp_h0 = Wh0 + c0 + (size_t)p * HH + cgo;
    const float* wp_i1 = Wi1 + c0 + (size_t)p * HH + cgo;
    const float* wp_h1 = Wh1 + c0 + (size_t)p * HH + cgo;
    const float* hx_x  = h0x + p * HP + rqo;           // x rows 0..63
    const float* hx_h0 = h0x + (64 + p) * HP + rqo;    // h0n rows
    const float* hx_h1 = h1x + p * HP + rqo;

    // ---- init ----
    sg0[tid] = g0[tid];  sb0[tid] = be0[tid];
    sg1[tid] = g1[tid];  sb1[tid] = be1[tid];
    if (tid < CW) {
        cb0[tid] = bi0[c0 + tid] + bh0[c0 + tid];
        cb1[tid] = bi1[c0 + tid] + bh1[c0 + tid];
    }
    for (int i = tid; i < 576 * HP; i += NTHR) h0x[i] = 0.f;
    for (int i = tid; i < 512 * HP; i += NTHR) h1x[i] = 0.f;
    __syncthreads();
    CL_ARRIVE();     // pairs with the E1(t-1) wait of step 0; also publishes init

    for (int t = 0; t < TSTEPS; ++t) {
        // ---- stage x_t ----
        {
            int r = tid >> 6, k = tid & 63;
            h0x[k * HP + r] = x[((size_t)(row0 + r) * TSTEPS + t) * DIN + k];
        }
        __syncthreads();

        // ---- G0: x·Wi0 + h0n(t-1)·Wh0  (overlaps E1(t-1) exchange) ----
        ull acc[8];
#pragma unroll
        for (int q = 0; q < 8; ++q) acc[q] = 0ull;
        gpart<4>(wp_i0, hx_x, acc);
        gpart<32>(wp_h0, hx_h0, acc);

        CL_WAIT();                       // E1(t-1): inbox[1], part[1] valid
        if (t > 0 && tid < 64) {         // LN stats for h1n(t-1)
            int r = (tid >> 5) * 4 + ((tid & 31) >> 3);
            int s8 = tid & 7;
            float2 pv = part[(NC + s8) * RG + r];
#pragma unroll
            for (int o = 4; o; o >>= 1) {
                pv.x += __shfl_xor_sync(0xffffffffu, pv.x, o);
                pv.y += __shfl_xor_sync(0xffffffffu, pv.y, o);
            }
            if (s8 == 0) {
                float mu = pv.x * (1.f / HH);
                float var = pv.y * (1.f / HH) - mu * mu;
                smu[r] = mu; srs[r] = rsqrtf(var + EPSF);
            }
        }
        __syncthreads();
        if (t > 0) {                     // rebuild h1n(t-1)
            float gk = sg1[tid], bk = sb1[tid];
            const float* ib = inbox + RG * HH + tid;
            float4 u, v;
            u.x = (ib[0 * HH] - smu[0]) * srs[0] * gk + bk;
            u.y = (ib[1 * HH] - smu[1]) * srs[1] * gk + bk;
            u.z = (ib[2 * HH] - smu[2]) * srs[2] * gk + bk;
            u.w = (ib[3 * HH] - smu[3]) * srs[3] * gk + bk;
            v.x = (ib[4 * HH] - smu[4]) * srs[4] * gk + bk;
            v.y = (ib[5 * HH] - smu[5]) * srs[5] * gk + bk;
            v.z = (ib[6 * HH] - smu[6]) * srs[6] * gk + bk;
            v.w = (ib[7 * HH] - smu[7]) * srs[7] * gk + bk;
            *(float4*)(h1x + tid * HP) = u;
            *(float4*)(h1x + tid * HP + 4) = v;
        }
        // dump acc0 -> red (same region, no conflict with rebuild)
        {
            float* rw = red + p * 576 + lane * 18;
#pragma unroll
            for (int q = 0; q < 8; ++q) *(ull*)(rw + 2 * q) = acc[q];
        }
        __syncthreads();

        // ---- epilogue 0 ----
        {
            float z = 0.f;
#pragma unroll
            for (int i = 0; i < 16; ++i) z += rrd[i * 576];
            z += cb0[ecol];
            float cv = tanhf(z) + h0x[(64 + c0 + ecol) * HP + erow];
            inbox[erow * HH + c0 + ecol] = cv;
            float s = cv, q = cv * cv;
#pragma unroll
            for (int o = 16; o; o >>= 1) {
                s += __shfl_xor_sync(0xffffffffu, s, o);
                q += __shfl_xor_sync(0xffffffffu, q, o);
            }
            if (lane == 0) sp[p] = make_float2(s, q);
        }
        __syncthreads();
        if (tid < RG) {
            float2 a = sp[2 * tid], b = sp[2 * tid + 1];
            float2 pv = make_float2(a.x + b.x, a.y + b.y);
            part[rank * RG + tid] = pv;
            uint32_t off = (uint32_t)((rank * RG + tid) * 8);
            ull pb = *(ull*)&pv;
#pragma unroll
            for (int d = 1; d < NC; ++d)
                st_cluster_b64(part_b + off, (rank + d) & (NC - 1), pb);
        }
        if (tid < 128) {
            int rr = tid >> 4, cgi = tid & 15;
            int fo = rr * HH + c0 + 4 * cgi;
            float4 v = *(const float4*)(inbox + fo);
            uint32_t off = (uint32_t)(fo * 4);
#pragma unroll
            for (int d = 1; d < NC; ++d)
                st_cluster_v4(inbox_b + off, (rank + d) & (NC - 1), v);
        }
        CL_ARRIVE();                     // E0(t)

        // ---- G1a: h1n(t-1)·Wh1  (overlaps E0 exchange) ----
#pragma unroll
        for (int q = 0; q < 8; ++q) acc[q] = 0ull;
        gpart<32>(wp_h1, hx_h1, acc);

        CL_WAIT();                       // E0(t): inbox[0], part[0] valid
        if (tid < 64) {                  // LN stats for h0n(t)
            int r = (tid >> 5) * 4 + ((tid & 31) >> 3);
            int s8 = tid & 7;
            float2 pv = part[s8 * RG + r];
#pragma unroll
            for (int o = 4; o; o >>= 1) {
                pv.x += __shfl_xor_sync(0xffffffffu, pv.x, o);
                pv.y += __shfl_xor_sync(0xffffffffu, pv.y, o);
            }
            if (s8 == 0) {
                float mu = pv.x * (1.f / HH);
                float var = pv.y * (1.f / HH) - mu * mu;
                smu[r] = mu; srs[r] = rsqrtf(var + EPSF);
            }
        }
        __syncthreads();
        {                                // rebuild h0n(t)
            float gk = sg0[tid], bk = sb0[tid];
            const float* ib = inbox + tid;
            float4 u, v;
            u.x = (ib[0 * HH] - smu[0]) * srs[0] * gk + bk;
            u.y = (ib[1 * HH] - smu[1]) * srs[1] * gk + bk;
            u.z = (ib[2 * HH] - smu[2]) * srs[2] * gk + bk;
            u.w = (ib[3 * HH] - smu[3]) * srs[3] * gk + bk;
            v.x = (ib[4 * HH] - smu[4]) * srs[4] * gk + bk;
            v.y = (ib[5 * HH] - smu[5]) * srs[5] * gk + bk;
            v.z = (ib[6 * HH] - smu[6]) * srs[6] * gk + bk;
            v.w = (ib[7 * HH] - smu[7]) * srs[7] * gk + bk;
            *(float4*)(h0x + (64 + tid) * HP) = u;
            *(float4*)(h0x + (64 + tid) * HP + 4) = v;
        }
        __syncthreads();

        // ---- G1b: h0n(t)·Wi1 ----
        gpart<32>(wp_i1, hx_h0, acc);
        {
            float* rw = red + p * 576 + lane * 18;
#pragma unroll
            for (int q = 0; q < 8; ++q) *(ull*)(rw + 2 * q) = acc[q];
        }
        __syncthreads();

        // ---- epilogue 1 ----
        {
            float z = 0.f;
#pragma unroll
            for (int i = 0; i < 16; ++i) z += rrd[i * 576];
            z += cb1[ecol];
            float cv = tanhf(z) + h1x[(c0 + ecol) * HP + erow];
            inbox[RG * HH + erow * HH + c0 + ecol] = cv;
            float s = cv, q = cv * cv;
#pragma unroll
            for (int o = 16; o; o >>= 1) {
                s += __shfl_xor_sync(0xffffffffu, s, o);
                q += __shfl_xor_sync(0xffffffffu, q, o);
            }
            if (lane == 0) sp[p] = make_float2(s, q);
        }
        __syncthreads();
        if (tid < RG) {
            float2 a = sp[2 * tid], b = sp[2 * tid + 1];
            float2 pv = make_float2(a.x + b.x, a.y + b.y);
            part[(NC + rank) * RG + tid] = pv;
            uint32_t off = (uint32_t)(((NC + rank) * RG + tid) * 8);
            ull pb = *(ull*)&pv;
#pragma unroll
            for (int d = 1; d < NC; ++d)
                st_cluster_b64(part_b + off, (rank + d) & (NC - 1), pb);
        }
        if (tid < 128) {
            int rr = tid >> 4, cgi = tid & 15;
            int fo = RG * HH + rr * HH + c0 + 4 * cgi;
            float4 v = *(const float4*)(inbox + fo);
            uint32_t off = (uint32_t)(fo * 4);
#pragma unroll
            for (int d = 1; d < NC; ++d)
                st_cluster_v4(inbox_b + off, (rank + d) & (NC - 1), v);
        }
        CL_ARRIVE();                     // E1(t)
    }

    // ---- final: wait E1(T-1), rebuild h1n, output head ----
    CL_WAIT();
    if (tid < 64) {
        int r = (tid >> 5) * 4 + ((tid & 31) >> 3);
        int s8 = tid & 7;
        float2 pv = part[(NC + s8) * RG + r];
#pragma unroll
        for (int o = 4; o; o >>= 1) {
            pv.x += __shfl_xor_sync(0xffffffffu, pv.x, o);
            pv.y += __shfl_xor_sync(0xffffffffu, pv.y, o);
        }
        if (s8 == 0) {
            float mu = pv.x * (1.f / HH);
            float var = pv.y * (1.f / HH) - mu * mu;
            smu[r] = mu; srs[r] = rsqrtf(var + EPSF);
        }
    }
    __syncthreads();
    {
        float gk = sg1[tid], bk = sb1[tid];
        const float* ib = inbox + RG * HH + tid;
#pragma unroll
        for (int r = 0; r < RG; ++r)
            h1x[tid * HP + r] = (ib[r * HH] - smu[r]) * srs[r] * gk + bk;
    }
    __syncthreads();
    if (rank == 0 && p < RG) {
        float v = 0.f;
#pragma unroll
        for (int m = 0; m < 16; ++m) {
            int k = lane + 32 * m;
            v += h1x[k * HP + p] * Wfc[k];
        }
#pragma unroll
        for (int o = 16; o; o >>= 1) v += __shfl_xor_sync(0xffffffffu, v, o);
        if (lane == 0) out[row0 + p] = v + bfc[0];
    }
}

extern "C" void kernel_launch(void* const* d_in, const int* in_sizes, int n_in,
                              void* d_out, int out_size) {
    (void)in_sizes; (void)n_in; (void)out_size;
    const float* x   = (const float*)d_in[0];
    const float* Wi0 = (const float*)d_in[1];
    const float* bi0 = (const float*)d_in[2];
    const float* Wh0 = (const float*)d_in[3];
    const float* bh0 = (const float*)d_in[4];
    const float* g0  = (const float*)d_in[5];
    const float* be0 = (const float*)d_in[6];
    const float* Wi1 = (const float*)d_in[7];
    const float* bi1 = (const float*)d_in[8];
    const float* Wh1 = (const float*)d_in[9];
    const float* bh1 = (const float*)d_in[10];
    const float* g1  = (const float*)d_in[11];
    const float* be1 = (const float*)d_in[12];
    const float* Wfc = (const float*)d_in[13];
    const float* bfc = (const float*)d_in[14];

    static int inited = 0;
    if (!inited) {
        cudaFuncSetAttribute(rnn_overlap_kernel,
                             cudaFuncAttributeMaxDynamicSharedMemorySize, SMEM_BYTES);
        inited = 1;
    }
    rnn_overlap_kernel<<<NGRP * NC, NTHR, SMEM_BYTES>>>(
        x, Wi0, bi0, Wh0, bh0, g0, be0,
        Wi1, bi1, Wh1, bh1, g1, be1,
        Wfc, bfc, (float*)d_out);
}